// round 12
// baseline (speedup 1.0000x reference)
#include <cuda_runtime.h>
#include <cuda_bf16.h>
#include <math.h>
#include <stdint.h>

#define BATCH  8
#define CHN    128
#define HEADS  8
#define HC     16
#define NPIX   65536
#define EPS    1e-5f

#define PXA    64      // kernel A pixels per chunk
#define NCHA   8       // chunks per CTA (A)  -> 512 px/CTA
#define PXC    64      // kernel C pixels per chunk
#define NCHC   8       // chunks per CTA (C)  -> 512 px/CTA
#define WSTR   136     // bf16 row stride (272B): conflict-free ldmatrix
#define LNS    66      // LN buffer row stride (floats)

typedef unsigned long long ull;
typedef unsigned int u32;
typedef unsigned short u16;

// ---------------- persistent device scratch ----------------
__device__ float g_kv[BATCH * HEADS * HC * HC];                      // 16384 elems
__device__ __align__(16) __nv_bfloat16 g_wkv[2][256][WSTR];          // kv weights hi/lo
__device__ __align__(16) __nv_bfloat16 g_m1[BATCH][2][CHN][WSTR];    // fused M1 hi/lo
__device__ __align__(16) __nv_bfloat16 g_o2[2][CHN][WSTR];           // o2 hi/lo

// ---------------- helpers ----------------
static __device__ __forceinline__ ull fma2(ull a, ull b, ull c) {
    ull d;
    asm("fma.rn.f32x2 %0, %1, %2, %3;" : "=l"(d) : "l"(a), "l"(b), "l"(c));
    return d;
}
static __device__ __forceinline__ float2 unpack2(ull v) {
    float2 r;
    asm("mov.b64 {%0, %1}, %2;" : "=f"(r.x), "=f"(r.y) : "l"(v));
    return r;
}
static __device__ __forceinline__ float gelu_fast(float v) {
    float c = v * v;
    float t = v * (0.79788456f + 0.035677408f * c);
    float th;
    asm("tanh.approx.f32 %0, %1;" : "=f"(th) : "f"(t));
    return 0.5f * v * (1.f + th);
}
static __device__ __forceinline__ float sqrt_approx(float v) {
    float r;
    asm("sqrt.approx.f32 %0, %1;" : "=f"(r) : "f"(v));
    return r;
}
static __device__ __forceinline__ float rcp_approx(float v) {
    float r;
    asm("rcp.approx.f32 %0, %1;" : "=f"(r) : "f"(v));
    return r;
}
static __device__ __forceinline__ u32 pack_bf16x2(float a_hi, float a_lo) {
    u32 r;
    asm("cvt.rn.bf16x2.f32 %0, %1, %2;" : "=r"(r) : "f"(a_hi), "f"(a_lo));
    return r;
}
static __device__ __forceinline__ u32 smem_u32(const void* p) {
    u32 a;
    asm("{ .reg .u64 t; cvta.to.shared.u64 t, %1; cvt.u32.u64 %0, t; }" : "=r"(a) : "l"(p));
    return a;
}

#define LDSM4(r0, r1, r2, r3, a)                                           \
    asm volatile("ldmatrix.sync.aligned.m8n8.x4.shared.b16 {%0,%1,%2,%3}, [%4];" \
        : "=r"(r0), "=r"(r1), "=r"(r2), "=r"(r3) : "r"(a))

static __device__ __forceinline__ void mma16816(float* d, const u32* a, const u32* b) {
    asm volatile(
        "mma.sync.aligned.m16n8k16.row.col.f32.bf16.bf16.f32 "
        "{%0,%1,%2,%3}, {%4,%5,%6,%7}, {%8,%9}, {%0,%1,%2,%3};"
        : "+f"(d[0]), "+f"(d[1]), "+f"(d[2]), "+f"(d[3])
        : "r"(a[0]), "r"(a[1]), "r"(a[2]), "r"(a[3]), "r"(b[0]), "r"(b[1]));
}

static __device__ __forceinline__ void split_bf16(float w, __nv_bfloat16& hi, __nv_bfloat16& lo) {
    hi = __float2bfloat16(w);
    lo = __float2bfloat16(w - __bfloat162float(hi));
}
static __device__ __forceinline__ void split_pair(float v0, float v1, u32& h2, u32& l2) {
    h2 = pack_bf16x2(v1, v0);
    float h0 = __uint_as_float(h2 << 16);
    float h1 = __uint_as_float(h2 & 0xFFFF0000u);
    l2 = pack_bf16x2(v1 - h1, v0 - h0);
}

// ============================================================================
__global__ void zero_kv_kernel() {
    int i = blockIdx.x * blockDim.x + threadIdx.x;
    if (i < BATCH * HEADS * HC * HC) g_kv[i] = 0.f;
}

__global__ void prep_wkv_kernel(const float* __restrict__ qkv_w) {
    int idx = blockIdx.x * blockDim.x + threadIdx.x;   // 32768
    int o = idx >> 7, c = idx & 127;
    int row = (o >> 5) * 48 + 16 + (o & 31);
    __nv_bfloat16 hi, lo;
    split_bf16(qkv_w[row * CHN + c], hi, lo);
    g_wkv[0][o][c] = hi;
    g_wkv[1][o][c] = lo;
}

// ============================================================================
// Kernel A: k,v = W_kv @ x (mma.sync bf16, 3-term split), LN(16), kv outer.
// HEAD-SPLIT: each CTA handles 4 heads (128 k/v outputs) -> smem 105.5 KB
// -> 2 CTAs/SM; phases of co-resident CTAs overlap (tensor vs ALU pipes).
// Grid: x = (pixel_block<<1)|zhalf so the CTA pair shares L2 for x.
// 512 threads = 16 warps: 4(M) x 4(N); warp tile 32 out x 16 px; chunk 64 px.
// ============================================================================
__global__ void __launch_bounds__(512, 2) kv_accum_kernel(
    const float* __restrict__ x,
    const float* __restrict__ klw, const float* __restrict__ klb,
    const float* __restrict__ vlw, const float* __restrict__ vlb)
{
    extern __shared__ __align__(16) unsigned char sm[];
    const int OFF_WH = 0;          // 128*WSTR*2 = 34816
    const int OFF_WL = 34816;      // weights end 69632
    const int OFF_XH = 69632;      // 17408
    const int OFF_XL = 87040;      // X end 104448
    const int OFF_LN = 69632;      // overlay on X: 128*LNS*4 = 33792
    const int OFF_LW = 104448;     // 512B
    const int OFF_LB = 104960;     // 512B -> total 105472

    const u32 sbase = smem_u32(sm);
    float* lnbuf = (float*)(sm + OFF_LN);
    float* lw = (float*)(sm + OFF_LW);
    float* lb = (float*)(sm + OFF_LB);

    const int tid = threadIdx.x;
    const int wid = tid >> 5, lane = tid & 31;
    const int b = blockIdx.y;
    const int z = blockIdx.x & 1;                       // head half
    const int n0 = (blockIdx.x >> 1) * (PXA * NCHA);

    {   // weight images (this half's 128 rows, hi then lo) -> smem
        const float4* sh = (const float4*)&g_wkv[0][z * 128][0];  // 2176 float4
        const float4* sl = (const float4*)&g_wkv[1][z * 128][0];
        float4* dh = (float4*)(sm + OFF_WH);
        float4* dl = (float4*)(sm + OFF_WL);
        #pragma unroll
        for (int i = 0; i < 4; i++) {
            dh[tid + i * 512] = sh[tid + i * 512];
            dl[tid + i * 512] = sl[tid + i * 512];
        }
        if (tid < 128) {
            dh[tid + 2048] = sh[tid + 2048];
            dl[tid + 2048] = sl[tid + 2048];
        }
    }
    if (tid < 128) {
        int o = tid, gh = z * 4 + (o >> 5), d = o & 15;
        if (o & 16) { lw[o] = vlw[gh * HC + d]; lb[o] = vlb[gh * HC + d]; }
        else        { lw[o] = klw[gh * HC + d]; lb[o] = klb[gh * HC + d]; }
    }

    // warp GEMM mapping: 4(M) x 4(N), warp tile 32 out x 16 px
    const int wm = wid & 3, wn = wid >> 2;
    const int m_base = wm * 32, n_base = wn * 16;
    const u32 aoff = (u32)((m_base + (lane & 15)) * WSTR + (lane >> 4) * 8) * 2;
    const u32 boff = (u32)((n_base + (lane & 7) + (lane >> 4) * 8) * WSTR
                           + ((lane >> 3) & 1) * 8) * 2;

    // loader mapping: 2 adjacent channels x 8 px per thread
    const int lc2 = (tid & 63) * 2, lpx = (tid >> 6) * 8;
    const float* gx0 = x + ((size_t)b * CHN + lc2) * NPIX + lpx;
    const float* gx1 = gx0 + NPIX;
    // outer-product mapping: warp -> (local head, px quarter)
    const int hl = wid & 3, pq = (wid >> 2) * 16;
    const int odd = lane >> 1, oe0 = (lane & 1) * 8;

    ull kvacc[8];
    #pragma unroll
    for (int t = 0; t < 8; t++) kvacc[t] = 0ull;

    for (int ch = 0; ch < NCHA; ch++) {
        const int nb = n0 + ch * PXA;
        __syncthreads();   // lnbuf consumers done; weights/LN params visible

        {   // x tile -> X split (packed 4B stores); latency hidden by 2nd CTA
            const float4* g0 = (const float4*)(gx0 + nb);
            const float4* g1 = (const float4*)(gx1 + nb);
            float4 a0 = g0[0], a1 = g0[1], c0 = g1[0], c1 = g1[1];
            float v0[8] = {a0.x, a0.y, a0.z, a0.w, a1.x, a1.y, a1.z, a1.w};
            float v1[8] = {c0.x, c0.y, c0.z, c0.w, c1.x, c1.y, c1.z, c1.w};
            #pragma unroll
            for (int j = 0; j < 8; j++) {
                u32 h2, l2;
                split_pair(v0[j], v1[j], h2, l2);
                int boffj = ((lpx + j) * WSTR + lc2) * 2;
                *(u32*)(sm + OFF_XH + boffj) = h2;
                *(u32*)(sm + OFF_XL + boffj) = l2;
            }
        }
        __syncthreads();

        // GEMM: 2 m16 x 2 n8 tiles, K=128 in 8 steps, 3-term split
        float acc[2][2][4];
        #pragma unroll
        for (int i = 0; i < 2; i++)
            #pragma unroll
            for (int j = 0; j < 2; j++)
                #pragma unroll
                for (int q = 0; q < 4; q++) acc[i][j][q] = 0.f;

        #pragma unroll
        for (int ks = 0; ks < 8; ks++) {
            const u32 kk = ks * 32;
            u32 Ah[2][4], Al[2][4], Bh[4], Bl[4];
            LDSM4(Ah[0][0], Ah[0][1], Ah[0][2], Ah[0][3], sbase + OFF_WH + aoff + kk);
            LDSM4(Ah[1][0], Ah[1][1], Ah[1][2], Ah[1][3], sbase + OFF_WH + aoff + kk + 16 * WSTR * 2);
            LDSM4(Al[0][0], Al[0][1], Al[0][2], Al[0][3], sbase + OFF_WL + aoff + kk);
            LDSM4(Al[1][0], Al[1][1], Al[1][2], Al[1][3], sbase + OFF_WL + aoff + kk + 16 * WSTR * 2);
            LDSM4(Bh[0], Bh[1], Bh[2], Bh[3], sbase + OFF_XH + boff + kk);
            LDSM4(Bl[0], Bl[1], Bl[2], Bl[3], sbase + OFF_XL + boff + kk);
            #pragma unroll
            for (int i = 0; i < 2; i++) {
                #pragma unroll
                for (int j = 0; j < 2; j++) {
                    mma16816(acc[i][j], Ah[i], Bh + j * 2);
                    mma16816(acc[i][j], Al[i], Bh + j * 2);
                    mma16816(acc[i][j], Ah[i], Bl + j * 2);
                }
            }
        }
        __syncthreads();   // X reads done -> lnbuf overlay safe

        // D -> lnbuf[out][px] (stride LNS, 128 local rows)
        #pragma unroll
        for (int i = 0; i < 2; i++) {
            #pragma unroll
            for (int j = 0; j < 2; j++) {
                int px = n_base + j * 8 + (lane & 3) * 2;
                int o0 = m_base + i * 16 + (lane >> 2);
                *(float2*)&lnbuf[o0 * LNS + px]       = make_float2(acc[i][j][0], acc[i][j][1]);
                *(float2*)&lnbuf[(o0 + 8) * LNS + px] = make_float2(acc[i][j][2], acc[i][j][3]);
            }
        }
        __syncthreads();

        {   // LayerNorm: 512 tasks = 64 px x 4 heads x {k,v}
            int p = tid & 63, hh = (tid >> 6) & 3, part = tid >> 8;
            int rbase = hh * 32 + part * 16;
            float t[16]; float s = 0.f;
            #pragma unroll
            for (int d = 0; d < 16; d++) { t[d] = lnbuf[(rbase + d) * LNS + p]; s += t[d]; }
            float m = s * (1.f / 16.f);
            float var = 0.f;
            #pragma unroll
            for (int d = 0; d < 16; d++) { float dv = t[d] - m; var += dv * dv; }
            float inv = rcp_approx(sqrt_approx(var * (1.f / 15.f)) + EPS);
            #pragma unroll
            for (int d = 0; d < 16; d++)
                lnbuf[(rbase + d) * LNS + p] =
                    lw[rbase + d] * ((t[d] - m) * inv) + lb[rbase + d];
        }
        __syncthreads();

        {   // kv outer product (f32x2): warp -> (local head, 16-px quarter)
            const float* kr = &lnbuf[(hl * 32 + odd) * LNS + pq];
            #pragma unroll
            for (int p = 0; p < 16; p += 2) {
                ull k2 = *(const ull*)&kr[p];
                #pragma unroll
                for (int t = 0; t < 8; t++) {
                    ull v2 = *(const ull*)&lnbuf[(hl * 32 + 16 + oe0 + t) * LNS + pq + p];
                    kvacc[t] = fma2(k2, v2, kvacc[t]);
                }
            }
        }
    }

    #pragma unroll
    for (int t = 0; t < 8; t++) {
        float2 v = unpack2(kvacc[t]);
        atomicAdd(&g_kv[((b * HEADS + z * 4 + hl) * HC + odd) * HC + oe0 + t],
                  v.x + v.y);
    }
}

// ============================================================================
// Kernel B: fold attention -> M1[b] = o1_w @ (A + I); emit bf16 hi/lo images.
// grid (16 slices x 8 batches), 512 threads, 8 M1 rows per slice.
// ============================================================================
__global__ void build_mats_kernel(const float* __restrict__ qkv_w,
                                  const float* __restrict__ o1_w,
                                  const float* __restrict__ o2_w)
{
    extern __shared__ float smf[];
    float* kvs = smf;           // 2048
    float* As  = smf + 2048;    // [128][129]
    const int tid = threadIdx.x;
    const int slice = blockIdx.x;   // 0..15 -> 8 M1 rows each
    const int b     = blockIdx.y;

    for (int i = tid; i < HEADS * HC * HC; i += 512)
        kvs[i] = g_kv[b * HEADS * HC * HC + i] * (1.f / NPIX);
    __syncthreads();

    for (int idx = tid; idx < CHN * CHN; idx += 512) {
        int j = idx >> 7, c = idx & 127;
        int h = j >> 4, e = j & 15;
        float s = 0.f;
        #pragma unroll
        for (int d = 0; d < HC; d++)
            s += qkv_w[(h * 48 + d) * CHN + c] * kvs[(h * HC + d) * HC + e];
        As[j * 129 + c] = s;
    }
    __syncthreads();

    for (int idx = tid; idx < 8 * CHN; idx += 512) {
        int o = slice * 8 + (idx >> 7), c = idx & 127;
        float s = o1_w[o * CHN + c];   // identity term
        #pragma unroll 8
        for (int j = 0; j < CHN; j++)
            s += o1_w[o * CHN + j] * As[j * 129 + c];
        __nv_bfloat16 hi, lo;
        split_bf16(s, hi, lo);
        g_m1[b][0][o][c] = hi;
        g_m1[b][1][o][c] = lo;
    }
    if (b == 0) {
        for (int idx = tid; idx < 8 * CHN; idx += 512) {
            int o = slice * 8 + (idx >> 7), c = idx & 127;
            __nv_bfloat16 hi, lo;
            split_bf16(o2_w[o * CHN + c], hi, lo);
            g_o2[0][o][c] = hi;
            g_o2[1][o][c] = lo;
        }
    }
}

// ============================================================================
// Kernel C: out = gelu( o2 @ gelu( M1[b] @ x ) + x ), both GEMMs mma.sync.
// 512 threads = 16 warps: 4(M) x 4(N); warp tile 32 out x 16 px; chunk 64 px.
// X and U separate; epilogue2 residual reconstructed from X smem.
// ============================================================================
__global__ void __launch_bounds__(512, 1) mlp_kernel(
    const float* __restrict__ x, float* __restrict__ out)
{
    extern __shared__ __align__(16) unsigned char sm[];
    const int OFF_M1H = 0;          // 34816
    const int OFF_M1L = 34816;
    const int OFF_O2H = 69632;
    const int OFF_O2L = 104448;     // weights end 139264
    const int OFF_XH  = 139264;     // 17408
    const int OFF_XL  = 156672;     // X end 174080
    const int OFF_UH  = 174080;
    const int OFF_UL  = 191488;     // total 208896

    const u32 sbase = smem_u32(sm);
    const int tid = threadIdx.x;
    const int wid = tid >> 5, lane = tid & 31;
    const int b = blockIdx.y;
    const int n0 = blockIdx.x * (PXC * NCHC);

    {   // weight images -> smem: 4352 float4 each pair
        const float4* s1 = (const float4*)&g_m1[b][0][0][0];
        const float4* s2 = (const float4*)&g_o2[0][0][0];
        float4* d1 = (float4*)(sm + OFF_M1H);
        float4* d2 = (float4*)(sm + OFF_O2H);
        #pragma unroll
        for (int i = 0; i < 8; i++) {
            d1[tid + i * 512] = s1[tid + i * 512];
            d2[tid + i * 512] = s2[tid + i * 512];
        }
        if (tid < 256) {
            d1[tid + 4096] = s1[tid + 4096];
            d2[tid + 4096] = s2[tid + 4096];
        }
    }

    const int wm = wid & 3, wn = wid >> 2;
    const int m_base = wm * 32, n_base = wn * 16;
    const u32 aoff = (u32)((m_base + (lane & 15)) * WSTR + (lane >> 4) * 8) * 2;
    const u32 boff = (u32)((n_base + (lane & 7) + (lane >> 4) * 8) * WSTR
                           + ((lane >> 3) & 1) * 8) * 2;

    const int lc2 = (tid & 63) * 2, lpx = (tid >> 6) * 8;
    const float* gx0 = x + ((size_t)b * CHN + lc2) * NPIX + lpx;
    const float* gx1 = gx0 + NPIX;

    // prefetch chunk 0
    float vv0[8], vv1[8];
    {
        const float4* g0 = (const float4*)(gx0 + n0);
        const float4* g1 = (const float4*)(gx1 + n0);
        float4 a0 = g0[0], a1 = g0[1], c0 = g1[0], c1 = g1[1];
        vv0[0]=a0.x; vv0[1]=a0.y; vv0[2]=a0.z; vv0[3]=a0.w;
        vv0[4]=a1.x; vv0[5]=a1.y; vv0[6]=a1.z; vv0[7]=a1.w;
        vv1[0]=c0.x; vv1[1]=c0.y; vv1[2]=c0.z; vv1[3]=c0.w;
        vv1[4]=c1.x; vv1[5]=c1.y; vv1[6]=c1.z; vv1[7]=c1.w;
    }

    for (int ch = 0; ch < NCHC; ch++) {
        const int nb = n0 + ch * PXC;
        {   // current chunk regs -> X split (packed 4B stores)
            #pragma unroll
            for (int j = 0; j < 8; j++) {
                u32 h2, l2;
                split_pair(vv0[j], vv1[j], h2, l2);
                int boffj = ((lpx + j) * WSTR + lc2) * 2;
                *(u32*)(sm + OFF_XH + boffj) = h2;
                *(u32*)(sm + OFF_XL + boffj) = l2;
            }
        }
        if (ch + 1 < NCHC) {   // prefetch next chunk
            const float4* g0 = (const float4*)(gx0 + n0 + (ch + 1) * PXC);
            const float4* g1 = (const float4*)(gx1 + n0 + (ch + 1) * PXC);
            float4 a0 = g0[0], a1 = g0[1], c0 = g1[0], c1 = g1[1];
            vv0[0]=a0.x; vv0[1]=a0.y; vv0[2]=a0.z; vv0[3]=a0.w;
            vv0[4]=a1.x; vv0[5]=a1.y; vv0[6]=a1.z; vv0[7]=a1.w;
            vv1[0]=c0.x; vv1[1]=c0.y; vv1[2]=c0.z; vv1[3]=c0.w;
            vv1[4]=c1.x; vv1[5]=c1.y; vv1[6]=c1.z; vv1[7]=c1.w;
        }
        __syncthreads();

        // ---- GEMM1: D1 = M1 @ x ----
        float a1c[2][2][4];
        #pragma unroll
        for (int i = 0; i < 2; i++)
            #pragma unroll
            for (int j = 0; j < 2; j++)
                #pragma unroll
                for (int q = 0; q < 4; q++) a1c[i][j][q] = 0.f;

        #pragma unroll
        for (int ks = 0; ks < 8; ks++) {
            const u32 kk = ks * 32;
            u32 Ah[2][4], Al[2][4], Bh[4], Bl[4];
            LDSM4(Ah[0][0], Ah[0][1], Ah[0][2], Ah[0][3], sbase + OFF_M1H + aoff + kk);
            LDSM4(Ah[1][0], Ah[1][1], Ah[1][2], Ah[1][3], sbase + OFF_M1H + aoff + kk + 16 * WSTR * 2);
            LDSM4(Al[0][0], Al[0][1], Al[0][2], Al[0][3], sbase + OFF_M1L + aoff + kk);
            LDSM4(Al[1][0], Al[1][1], Al[1][2], Al[1][3], sbase + OFF_M1L + aoff + kk + 16 * WSTR * 2);
            LDSM4(Bh[0], Bh[1], Bh[2], Bh[3], sbase + OFF_XH + boff + kk);
            LDSM4(Bl[0], Bl[1], Bl[2], Bl[3], sbase + OFF_XL + boff + kk);
            #pragma unroll
            for (int i = 0; i < 2; i++)
                #pragma unroll
                for (int j = 0; j < 2; j++) {
                    mma16816(a1c[i][j], Ah[i], Bh + j * 2);
                    mma16816(a1c[i][j], Al[i], Bh + j * 2);
                    mma16816(a1c[i][j], Ah[i], Bl + j * 2);
                }
        }

        {   // epilogue1: u = gelu(D1), split, store transposed [px][chan] -> U
            __nv_bfloat16* uh = (__nv_bfloat16*)(sm + OFF_UH);
            __nv_bfloat16* ul = (__nv_bfloat16*)(sm + OFF_UL);
            #pragma unroll
            for (int i = 0; i < 2; i++)
                #pragma unroll
                for (int j = 0; j < 2; j++) {
                    int px = n_base + j * 8 + (lane & 3) * 2;
                    int o0 = m_base + i * 16 + (lane >> 2);
                    #pragma unroll
                    for (int q = 0; q < 4; q++) {
                        int pp = px + (q & 1);
                        int oo = o0 + (q >> 1) * 8;
                        float u = gelu_fast(a1c[i][j][q]);
                        __nv_bfloat16 hi, lo;
                        split_bf16(u, hi, lo);
                        uh[pp * WSTR + oo] = hi;
                        ul[pp * WSTR + oo] = lo;
                    }
                }
        }
        __syncthreads();

        // ---- GEMM2: D2 = o2 @ u ----
        float a2c[2][2][4];
        #pragma unroll
        for (int i = 0; i < 2; i++)
            #pragma unroll
            for (int j = 0; j < 2; j++)
                #pragma unroll
                for (int q = 0; q < 4; q++) a2c[i][j][q] = 0.f;

        #pragma unroll
        for (int ks = 0; ks < 8; ks++) {
            const u32 kk = ks * 32;
            u32 Ah[2][4], Al[2][4], Bh[4], Bl[4];
            LDSM4(Ah[0][0], Ah[0][1], Ah[0][2], Ah[0][3], sbase + OFF_O2H + aoff + kk);
            LDSM4(Ah[1][0], Ah[1][1], Ah[1][2], Ah[1][3], sbase + OFF_O2H + aoff + kk + 16 * WSTR * 2);
            LDSM4(Al[0][0], Al[0][1], Al[0][2], Al[0][3], sbase + OFF_O2L + aoff + kk);
            LDSM4(Al[1][0], Al[1][1], Al[1][2], Al[1][3], sbase + OFF_O2L + aoff + kk + 16 * WSTR * 2);
            LDSM4(Bh[0], Bh[1], Bh[2], Bh[3], sbase + OFF_UH + boff + kk);
            LDSM4(Bl[0], Bl[1], Bl[2], Bl[3], sbase + OFF_UL + boff + kk);
            #pragma unroll
            for (int i = 0; i < 2; i++)
                #pragma unroll
                for (int j = 0; j < 2; j++) {
                    mma16816(a2c[i][j], Ah[i], Bh + j * 2);
                    mma16816(a2c[i][j], Al[i], Bh + j * 2);
                    mma16816(a2c[i][j], Ah[i], Bl + j * 2);
                }
        }

        {   // epilogue2: out = gelu(D2 + x); residual rebuilt from X smem (hi+lo)
            const __nv_bfloat16* xh = (const __nv_bfloat16*)(sm + OFF_XH);
            const __nv_bfloat16* xl = (const __nv_bfloat16*)(sm + OFF_XL);
            #pragma unroll
            for (int i = 0; i < 2; i++)
                #pragma unroll
                for (int j = 0; j < 2; j++) {
                    int pxl = n_base + j * 8 + (lane & 3) * 2;
                    int o0 = m_base + i * 16 + (lane >> 2);
                    #pragma unroll
                    for (int half = 0; half < 2; half++) {
                        int oo = o0 + half * 8;
                        u32 h0 = *(const u16*)&xh[pxl * WSTR + oo];
                        u32 l0 = *(const u16*)&xl[pxl * WSTR + oo];
                        u32 h1 = *(const u16*)&xh[(pxl + 1) * WSTR + oo];
                        u32 l1 = *(const u16*)&xl[(pxl + 1) * WSTR + oo];
                        float xv0 = __uint_as_float(h0 << 16) + __uint_as_float(l0 << 16);
                        float xv1 = __uint_as_float(h1 << 16) + __uint_as_float(l1 << 16);
                        float2 r;
                        r.x = gelu_fast(a2c[i][j][half * 2 + 0] + xv0);
                        r.y = gelu_fast(a2c[i][j][half * 2 + 1] + xv1);
                        *(float2*)(out + ((size_t)b * CHN + oo) * NPIX + nb + pxl) = r;
                    }
                }
        }
        __syncthreads();   // U reads (GEMM2) + X reads (E2) done before next chunk
    }
}

// ============================================================================
extern "C" void kernel_launch(void* const* d_in, const int* in_sizes, int n_in,
                              void* d_out, int out_size) {
    const float* x     = (const float*)d_in[0];
    const float* qkv_w = (const float*)d_in[1];
    const float* o1_w  = (const float*)d_in[2];
    const float* o2_w  = (const float*)d_in[3];
    const float* klw   = (const float*)d_in[4];
    const float* klb   = (const float*)d_in[5];
    const float* vlw   = (const float*)d_in[6];
    const float* vlb   = (const float*)d_in[7];
    float* out = (float*)d_out;

    const int SMEM_A = 105472;
    const int SMEM_B = (2048 + 128 * 129) * (int)sizeof(float);
    const int SMEM_C = 208896;

    cudaFuncSetAttribute(kv_accum_kernel,   cudaFuncAttributeMaxDynamicSharedMemorySize, SMEM_A);
    cudaFuncSetAttribute(build_mats_kernel, cudaFuncAttributeMaxDynamicSharedMemorySize, SMEM_B);
    cudaFuncSetAttribute(mlp_kernel,        cudaFuncAttributeMaxDynamicSharedMemorySize, SMEM_C);

    zero_kv_kernel<<<32, 512>>>();
    prep_wkv_kernel<<<64, 512>>>(qkv_w);
    // grid.x = (pixel_block << 1) | head_half -> pair adjacency for L2 reuse
    kv_accum_kernel<<<dim3(2 * (NPIX / (PXA * NCHA)), BATCH), 512, SMEM_A>>>(
        x, klw, klb, vlw, vlb);
    build_mats_kernel<<<dim3(16, BATCH), 512, SMEM_B>>>(qkv_w, o1_w, o2_w);
    mlp_kernel<<<dim3(NPIX / (PXC * NCHC), BATCH), 512, SMEM_C>>>(x, out);
}

// round 13
// speedup vs baseline: 1.0811x; 1.0811x over previous
#include <cuda_runtime.h>
#include <cuda_bf16.h>
#include <math.h>
#include <stdint.h>

#define BATCH  8
#define CHN    128
#define HEADS  8
#define HC     16
#define NPIX   65536
#define EPS    1e-5f

#define PXA    64      // kernel A pixels per chunk
#define NCHA   8       // chunks per CTA (A)  -> 512 px/CTA
#define PXC    128     // mlp pixels per chunk (1024 threads)
#define NCHC   4       // chunks per CTA (C)  -> 512 px/CTA
#define WSTR   136     // bf16 row stride (272B): conflict-free ldmatrix
#define LNS    66      // LN buffer row stride (floats)

typedef unsigned long long ull;
typedef unsigned int u32;
typedef unsigned short u16;

// ---------------- persistent device scratch ----------------
__device__ float g_kv[BATCH * HEADS * HC * HC];                      // 16384 elems
__device__ __align__(16) __nv_bfloat16 g_wkv[2][256][WSTR];          // kv weights hi/lo
__device__ __align__(16) __nv_bfloat16 g_m1[BATCH][2][CHN][WSTR];    // fused M1 hi/lo
__device__ __align__(16) __nv_bfloat16 g_o2[2][CHN][WSTR];           // o2 hi/lo

// ---------------- helpers ----------------
static __device__ __forceinline__ ull fma2(ull a, ull b, ull c) {
    ull d;
    asm("fma.rn.f32x2 %0, %1, %2, %3;" : "=l"(d) : "l"(a), "l"(b), "l"(c));
    return d;
}
static __device__ __forceinline__ float2 unpack2(ull v) {
    float2 r;
    asm("mov.b64 {%0, %1}, %2;" : "=f"(r.x), "=f"(r.y) : "l"(v));
    return r;
}
static __device__ __forceinline__ float gelu_fast(float v) {
    float c = v * v;
    float t = v * (0.79788456f + 0.035677408f * c);
    float th;
    asm("tanh.approx.f32 %0, %1;" : "=f"(th) : "f"(t));
    return 0.5f * v * (1.f + th);
}
static __device__ __forceinline__ float sqrt_approx(float v) {
    float r;
    asm("sqrt.approx.f32 %0, %1;" : "=f"(r) : "f"(v));
    return r;
}
static __device__ __forceinline__ float rcp_approx(float v) {
    float r;
    asm("rcp.approx.f32 %0, %1;" : "=f"(r) : "f"(v));
    return r;
}
static __device__ __forceinline__ u32 pack_bf16x2(float a_hi, float a_lo) {
    u32 r;
    asm("cvt.rn.bf16x2.f32 %0, %1, %2;" : "=r"(r) : "f"(a_hi), "f"(a_lo));
    return r;
}
static __device__ __forceinline__ u32 smem_u32(const void* p) {
    u32 a;
    asm("{ .reg .u64 t; cvta.to.shared.u64 t, %1; cvt.u32.u64 %0, t; }" : "=r"(a) : "l"(p));
    return a;
}

#define LDSM4(r0, r1, r2, r3, a)                                           \
    asm volatile("ldmatrix.sync.aligned.m8n8.x4.shared.b16 {%0,%1,%2,%3}, [%4];" \
        : "=r"(r0), "=r"(r1), "=r"(r2), "=r"(r3) : "r"(a))

static __device__ __forceinline__ void mma16816(float* d, const u32* a, const u32* b) {
    asm volatile(
        "mma.sync.aligned.m16n8k16.row.col.f32.bf16.bf16.f32 "
        "{%0,%1,%2,%3}, {%4,%5,%6,%7}, {%8,%9}, {%0,%1,%2,%3};"
        : "+f"(d[0]), "+f"(d[1]), "+f"(d[2]), "+f"(d[3])
        : "r"(a[0]), "r"(a[1]), "r"(a[2]), "r"(a[3]), "r"(b[0]), "r"(b[1]));
}

static __device__ __forceinline__ void split_bf16(float w, __nv_bfloat16& hi, __nv_bfloat16& lo) {
    hi = __float2bfloat16(w);
    lo = __float2bfloat16(w - __bfloat162float(hi));
}
static __device__ __forceinline__ void split_pair(float v0, float v1, u32& h2, u32& l2) {
    h2 = pack_bf16x2(v1, v0);
    float h0 = __uint_as_float(h2 << 16);
    float h1 = __uint_as_float(h2 & 0xFFFF0000u);
    l2 = pack_bf16x2(v1 - h1, v0 - h0);
}

// ============================================================================
__global__ void zero_kv_kernel() {
    int i = blockIdx.x * blockDim.x + threadIdx.x;
    if (i < BATCH * HEADS * HC * HC) g_kv[i] = 0.f;
}

__global__ void prep_wkv_kernel(const float* __restrict__ qkv_w) {
    int idx = blockIdx.x * blockDim.x + threadIdx.x;   // 32768
    int o = idx >> 7, c = idx & 127;
    int row = (o >> 5) * 48 + 16 + (o & 31);
    __nv_bfloat16 hi, lo;
    split_bf16(qkv_w[row * CHN + c], hi, lo);
    g_wkv[0][o][c] = hi;
    g_wkv[1][o][c] = lo;
}

// ============================================================================
// Kernel A (round-11 best): k,v GEMM + LN(16) + kv outer product.
// 512 threads = 16 warps: 8(M) x 2(N); warp tile 32 out x 32 px; chunk 64 px.
// ============================================================================
__global__ void __launch_bounds__(512, 1) kv_accum_kernel(
    const float* __restrict__ x,
    const float* __restrict__ klw, const float* __restrict__ klb,
    const float* __restrict__ vlw, const float* __restrict__ vlb)
{
    extern __shared__ __align__(16) unsigned char sm[];
    const int OFF_WH = 0;          // 69632
    const int OFF_WL = 69632;      // weights end 139264
    const int OFF_XH = 139264;     // 17408
    const int OFF_XL = 156672;     // X end 174080
    const int OFF_LN = 139264;     // overlay: 256*LNS*4 = 67584, ends 206848
    const int OFF_LW = 206848;
    const int OFF_LB = 207872;     // total 208896

    const u32 sbase = smem_u32(sm);
    float* lnbuf = (float*)(sm + OFF_LN);
    float* lw = (float*)(sm + OFF_LW);
    float* lb = (float*)(sm + OFF_LB);

    const int tid = threadIdx.x;
    const int wid = tid >> 5, lane = tid & 31;
    const int b = blockIdx.y;
    const int n0 = blockIdx.x * (PXA * NCHA);

    {   // weight images -> smem (8704 float4 = 17*512)
        const float4* src = (const float4*)&g_wkv[0][0][0];
        float4* dst = (float4*)(sm + OFF_WH);
        #pragma unroll
        for (int i = 0; i < 17; i++) dst[tid + i * 512] = src[tid + i * 512];
    }
    if (tid < 256) {
        int o = tid, h = o >> 5, d = o & 15;
        if (o & 16) { lw[o] = vlw[h * HC + d]; lb[o] = vlb[h * HC + d]; }
        else        { lw[o] = klw[h * HC + d]; lb[o] = klb[h * HC + d]; }
    }

    const int wm = wid & 7, wn = wid >> 3;
    const int m_base = wm * 32, n_base = wn * 32;
    const u32 aoff = (u32)((m_base + (lane & 15)) * WSTR + (lane >> 4) * 8) * 2;
    const u32 boff = (u32)((n_base + (lane & 7) + (lane >> 4) * 8) * WSTR
                           + ((lane >> 3) & 1) * 8) * 2;

    const int lc2 = (tid & 63) * 2, lpx = (tid >> 6) * 8;
    const float* gx0 = x + ((size_t)b * CHN + lc2) * NPIX + lpx;
    const float* gx1 = gx0 + NPIX;
    const int ohead = wid & 7, ophalf = (wid >> 3) * 32;
    const int odd = lane >> 1, oe0 = (lane & 1) * 8;

    ull kvacc[8];
    #pragma unroll
    for (int t = 0; t < 8; t++) kvacc[t] = 0ull;

    // prefetch chunk 0
    float vv0[8], vv1[8];
    {
        const float4* g0 = (const float4*)(gx0 + n0);
        const float4* g1 = (const float4*)(gx1 + n0);
        float4 a0 = g0[0], a1 = g0[1], c0 = g1[0], c1 = g1[1];
        vv0[0]=a0.x; vv0[1]=a0.y; vv0[2]=a0.z; vv0[3]=a0.w;
        vv0[4]=a1.x; vv0[5]=a1.y; vv0[6]=a1.z; vv0[7]=a1.w;
        vv1[0]=c0.x; vv1[1]=c0.y; vv1[2]=c0.z; vv1[3]=c0.w;
        vv1[4]=c1.x; vv1[5]=c1.y; vv1[6]=c1.z; vv1[7]=c1.w;
    }

    for (int ch = 0; ch < NCHA; ch++) {
        __syncthreads();

        {   // current chunk regs -> X split (packed 4B stores)
            #pragma unroll
            for (int j = 0; j < 8; j++) {
                u32 h2, l2;
                split_pair(vv0[j], vv1[j], h2, l2);
                int boffj = ((lpx + j) * WSTR + lc2) * 2;
                *(u32*)(sm + OFF_XH + boffj) = h2;
                *(u32*)(sm + OFF_XL + boffj) = l2;
            }
        }
        if (ch + 1 < NCHA) {
            const float4* g0 = (const float4*)(gx0 + n0 + (ch + 1) * PXA);
            const float4* g1 = (const float4*)(gx1 + n0 + (ch + 1) * PXA);
            float4 a0 = g0[0], a1 = g0[1], c0 = g1[0], c1 = g1[1];
            vv0[0]=a0.x; vv0[1]=a0.y; vv0[2]=a0.z; vv0[3]=a0.w;
            vv0[4]=a1.x; vv0[5]=a1.y; vv0[6]=a1.z; vv0[7]=a1.w;
            vv1[0]=c0.x; vv1[1]=c0.y; vv1[2]=c0.z; vv1[3]=c0.w;
            vv1[4]=c1.x; vv1[5]=c1.y; vv1[6]=c1.z; vv1[7]=c1.w;
        }
        __syncthreads();

        float acc[2][4][4];
        #pragma unroll
        for (int i = 0; i < 2; i++)
            #pragma unroll
            for (int j = 0; j < 4; j++)
                #pragma unroll
                for (int q = 0; q < 4; q++) acc[i][j][q] = 0.f;

        #pragma unroll
        for (int ks = 0; ks < 8; ks++) {
            const u32 kk = ks * 32;
            u32 Ah[2][4], Al[2][4], Bh[8], Bl[8];
            LDSM4(Ah[0][0], Ah[0][1], Ah[0][2], Ah[0][3], sbase + OFF_WH + aoff + kk);
            LDSM4(Ah[1][0], Ah[1][1], Ah[1][2], Ah[1][3], sbase + OFF_WH + aoff + kk + 16 * WSTR * 2);
            LDSM4(Al[0][0], Al[0][1], Al[0][2], Al[0][3], sbase + OFF_WL + aoff + kk);
            LDSM4(Al[1][0], Al[1][1], Al[1][2], Al[1][3], sbase + OFF_WL + aoff + kk + 16 * WSTR * 2);
            LDSM4(Bh[0], Bh[1], Bh[2], Bh[3], sbase + OFF_XH + boff + kk);
            LDSM4(Bh[4], Bh[5], Bh[6], Bh[7], sbase + OFF_XH + boff + kk + 16 * WSTR * 2);
            LDSM4(Bl[0], Bl[1], Bl[2], Bl[3], sbase + OFF_XL + boff + kk);
            LDSM4(Bl[4], Bl[5], Bl[6], Bl[7], sbase + OFF_XL + boff + kk + 16 * WSTR * 2);
            #pragma unroll
            for (int i = 0; i < 2; i++) {
                #pragma unroll
                for (int j = 0; j < 4; j++) {
                    mma16816(acc[i][j], Ah[i], Bh + j * 2);
                    mma16816(acc[i][j], Al[i], Bh + j * 2);
                    mma16816(acc[i][j], Ah[i], Bl + j * 2);
                }
            }
        }
        __syncthreads();

        #pragma unroll
        for (int i = 0; i < 2; i++) {
            #pragma unroll
            for (int j = 0; j < 4; j++) {
                int px = n_base + j * 8 + (lane & 3) * 2;
                int o0 = m_base + i * 16 + (lane >> 2);
                *(float2*)&lnbuf[o0 * LNS + px]       = make_float2(acc[i][j][0], acc[i][j][1]);
                *(float2*)&lnbuf[(o0 + 8) * LNS + px] = make_float2(acc[i][j][2], acc[i][j][3]);
            }
        }
        __syncthreads();

        {   // LayerNorm
            int p = tid & 63, hh = (tid >> 6) & 7;
            #pragma unroll
            for (int part = 0; part < 2; part++) {
                int rbase = hh * 32 + part * 16;
                float t[16]; float s = 0.f;
                #pragma unroll
                for (int d = 0; d < 16; d++) { t[d] = lnbuf[(rbase + d) * LNS + p]; s += t[d]; }
                float m = s * (1.f / 16.f);
                float var = 0.f;
                #pragma unroll
                for (int d = 0; d < 16; d++) { float dv = t[d] - m; var += dv * dv; }
                float inv = rcp_approx(sqrt_approx(var * (1.f / 15.f)) + EPS);
                #pragma unroll
                for (int d = 0; d < 16; d++)
                    lnbuf[(rbase + d) * LNS + p] =
                        lw[rbase + d] * ((t[d] - m) * inv) + lb[rbase + d];
            }
        }
        __syncthreads();

        {   // kv outer product
            const float* kr = &lnbuf[(ohead * 32 + odd) * LNS + ophalf];
            #pragma unroll
            for (int p = 0; p < 32; p += 2) {
                ull k2 = *(const ull*)&kr[p];
                #pragma unroll
                for (int t = 0; t < 8; t++) {
                    ull v2 = *(const ull*)&lnbuf[(ohead * 32 + 16 + oe0 + t) * LNS + ophalf + p];
                    kvacc[t] = fma2(k2, v2, kvacc[t]);
                }
            }
        }
    }

    #pragma unroll
    for (int t = 0; t < 8; t++) {
        float2 v = unpack2(kvacc[t]);
        atomicAdd(&g_kv[((b * HEADS + ohead) * HC + odd) * HC + oe0 + t], v.x + v.y);
    }
}

// ============================================================================
// Kernel B (16-slice best): M1[b] = o1_w @ (A + I); bf16 hi/lo images.
// ============================================================================
__global__ void build_mats_kernel(const float* __restrict__ qkv_w,
                                  const float* __restrict__ o1_w,
                                  const float* __restrict__ o2_w)
{
    extern __shared__ float smf[];
    float* kvs = smf;           // 2048
    float* As  = smf + 2048;    // [128][129]
    const int tid = threadIdx.x;
    const int slice = blockIdx.x;   // 0..15 -> 8 M1 rows each
    const int b     = blockIdx.y;

    for (int i = tid; i < HEADS * HC * HC; i += 512)
        kvs[i] = g_kv[b * HEADS * HC * HC + i] * (1.f / NPIX);
    __syncthreads();

    for (int idx = tid; idx < CHN * CHN; idx += 512) {
        int j = idx >> 7, c = idx & 127;
        int h = j >> 4, e = j & 15;
        float s = 0.f;
        #pragma unroll
        for (int d = 0; d < HC; d++)
            s += qkv_w[(h * 48 + d) * CHN + c] * kvs[(h * HC + d) * HC + e];
        As[j * 129 + c] = s;
    }
    __syncthreads();

    for (int idx = tid; idx < 8 * CHN; idx += 512) {
        int o = slice * 8 + (idx >> 7), c = idx & 127;
        float s = o1_w[o * CHN + c];   // identity term
        #pragma unroll 8
        for (int j = 0; j < CHN; j++)
            s += o1_w[o * CHN + j] * As[j * 129 + c];
        __nv_bfloat16 hi, lo;
        split_bf16(s, hi, lo);
        g_m1[b][0][o][c] = hi;
        g_m1[b][1][o][c] = lo;
    }
    if (b == 0) {
        for (int idx = tid; idx < 8 * CHN; idx += 512) {
            int o = slice * 8 + (idx >> 7), c = idx & 127;
            __nv_bfloat16 hi, lo;
            split_bf16(o2_w[o * CHN + c], hi, lo);
            g_o2[0][o][c] = hi;
            g_o2[1][o][c] = lo;
        }
    }
}

// ============================================================================
// Kernel C: out = gelu( o2 @ gelu( M1[b] @ x ) + x ), both GEMMs mma.sync.
// 1024 threads = 32 warps: 4(M) x 8(N); warp tile 32 out x 16 px; chunk 128 px.
// U overlays X; E2 residual from gmem. No register prefetch (32 warps hide it).
// ============================================================================
__global__ void __launch_bounds__(1024, 1) mlp_kernel(
    const float* __restrict__ x, float* __restrict__ out)
{
    extern __shared__ __align__(16) unsigned char sm[];
    const int OFF_M1H = 0;          // 34816
    const int OFF_M1L = 34816;
    const int OFF_O2H = 69632;
    const int OFF_O2L = 104448;     // weights end 139264
    const int OFF_XH  = 139264;     // 128*WSTR*2 = 34816
    const int OFF_XL  = 174080;     // X end 208896
    const int OFF_UH  = 139264;     // overlay on X
    const int OFF_UL  = 174080;     // total 208896

    const u32 sbase = smem_u32(sm);
    const int tid = threadIdx.x;
    const int wid = tid >> 5, lane = tid & 31;
    const int b = blockIdx.y;
    const int n0 = blockIdx.x * (PXC * NCHC);

    {   // weight images -> smem: 4352 float4 each pair (1024 thr: 4*1024 + 256)
        const float4* s1 = (const float4*)&g_m1[b][0][0][0];
        const float4* s2 = (const float4*)&g_o2[0][0][0];
        float4* d1 = (float4*)(sm + OFF_M1H);
        float4* d2 = (float4*)(sm + OFF_O2H);
        #pragma unroll
        for (int i = 0; i < 4; i++) {
            d1[tid + i * 1024] = s1[tid + i * 1024];
            d2[tid + i * 1024] = s2[tid + i * 1024];
        }
        if (tid < 256) {
            d1[tid + 4096] = s1[tid + 4096];
            d2[tid + 4096] = s2[tid + 4096];
        }
    }

    // warp mapping: 4(M) x 8(N), warp tile 32 out x 16 px
    const int wm = wid & 3, wn = wid >> 2;
    const int m_base = wm * 32, n_base = wn * 16;
    const u32 aoff = (u32)((m_base + (lane & 15)) * WSTR + (lane >> 4) * 8) * 2;
    const u32 boff = (u32)((n_base + (lane & 7) + (lane >> 4) * 8) * WSTR
                           + ((lane >> 3) & 1) * 8) * 2;

    // loader mapping: 2 adjacent channels x 8 px per thread (128 px total)
    const int lc2 = (tid & 63) * 2, lpx = (tid >> 6) * 8;
    const float* gx0 = x + ((size_t)b * CHN + lc2) * NPIX + lpx;
    const float* gx1 = gx0 + NPIX;

    for (int ch = 0; ch < NCHC; ch++) {
        const int nb = n0 + ch * PXC;
        __syncthreads();   // U reads (GEMM2 prev chunk) done -> X overlay safe

        {   // x tile -> X split (packed 4B stores); no prefetch, 32 warps hide it
            const float4* g0 = (const float4*)(gx0 + nb);
            const float4* g1 = (const float4*)(gx1 + nb);
            float4 a0 = g0[0], a1 = g0[1], c0 = g1[0], c1 = g1[1];
            float v0[8] = {a0.x, a0.y, a0.z, a0.w, a1.x, a1.y, a1.z, a1.w};
            float v1[8] = {c0.x, c0.y, c0.z, c0.w, c1.x, c1.y, c1.z, c1.w};
            #pragma unroll
            for (int j = 0; j < 8; j++) {
                u32 h2, l2;
                split_pair(v0[j], v1[j], h2, l2);
                int boffj = ((lpx + j) * WSTR + lc2) * 2;
                *(u32*)(sm + OFF_XH + boffj) = h2;
                *(u32*)(sm + OFF_XL + boffj) = l2;
            }
        }
        __syncthreads();

        // ---- GEMM1: D1 = M1 @ x ----
        float a1c[2][2][4];
        #pragma unroll
        for (int i = 0; i < 2; i++)
            #pragma unroll
            for (int j = 0; j < 2; j++)
                #pragma unroll
                for (int q = 0; q < 4; q++) a1c[i][j][q] = 0.f;

        #pragma unroll
        for (int ks = 0; ks < 8; ks++) {
            const u32 kk = ks * 32;
            u32 Ah[2][4], Al[2][4], Bh[4], Bl[4];
            LDSM4(Ah[0][0], Ah[0][1], Ah[0][2], Ah[0][3], sbase + OFF_M1H + aoff + kk);
            LDSM4(Ah[1][0], Ah[1][1], Ah[1][2], Ah[1][3], sbase + OFF_M1H + aoff + kk + 16 * WSTR * 2);
            LDSM4(Al[0][0], Al[0][1], Al[0][2], Al[0][3], sbase + OFF_M1L + aoff + kk);
            LDSM4(Al[1][0], Al[1][1], Al[1][2], Al[1][3], sbase + OFF_M1L + aoff + kk + 16 * WSTR * 2);
            LDSM4(Bh[0], Bh[1], Bh[2], Bh[3], sbase + OFF_XH + boff + kk);
            LDSM4(Bl[0], Bl[1], Bl[2], Bl[3], sbase + OFF_XL + boff + kk);
            #pragma unroll
            for (int i = 0; i < 2; i++)
                #pragma unroll
                for (int j = 0; j < 2; j++) {
                    mma16816(a1c[i][j], Ah[i], Bh + j * 2);
                    mma16816(a1c[i][j], Al[i], Bh + j * 2);
                    mma16816(a1c[i][j], Ah[i], Bl + j * 2);
                }
        }
        __syncthreads();   // X reads done -> U overlay safe

        {   // epilogue1: u = gelu(D1), split, store transposed [px][chan] -> U
            __nv_bfloat16* uh = (__nv_bfloat16*)(sm + OFF_UH);
            __nv_bfloat16* ul = (__nv_bfloat16*)(sm + OFF_UL);
            #pragma unroll
            for (int i = 0; i < 2; i++)
                #pragma unroll
                for (int j = 0; j < 2; j++) {
                    int px = n_base + j * 8 + (lane & 3) * 2;
                    int o0 = m_base + i * 16 + (lane >> 2);
                    #pragma unroll
                    for (int q = 0; q < 4; q++) {
                        int pp = px + (q & 1);
                        int oo = o0 + (q >> 1) * 8;
                        float u = gelu_fast(a1c[i][j][q]);
                        __nv_bfloat16 hi, lo;
                        split_bf16(u, hi, lo);
                        uh[pp * WSTR + oo] = hi;
                        ul[pp * WSTR + oo] = lo;
                    }
                }
        }
        __syncthreads();

        // ---- GEMM2: D2 = o2 @ u ----
        float a2c[2][2][4];
        #pragma unroll
        for (int i = 0; i < 2; i++)
            #pragma unroll
            for (int j = 0; j < 2; j++)
                #pragma unroll
                for (int q = 0; q < 4; q++) a2c[i][j][q] = 0.f;

        #pragma unroll
        for (int ks = 0; ks < 8; ks++) {
            const u32 kk = ks * 32;
            u32 Ah[2][4], Al[2][4], Bh[4], Bl[4];
            LDSM4(Ah[0][0], Ah[0][1], Ah[0][2], Ah[0][3], sbase + OFF_O2H + aoff + kk);
            LDSM4(Ah[1][0], Ah[1][1], Ah[1][2], Ah[1][3], sbase + OFF_O2H + aoff + kk + 16 * WSTR * 2);
            LDSM4(Al[0][0], Al[0][1], Al[0][2], Al[0][3], sbase + OFF_O2L + aoff + kk);
            LDSM4(Al[1][0], Al[1][1], Al[1][2], Al[1][3], sbase + OFF_O2L + aoff + kk + 16 * WSTR * 2);
            LDSM4(Bh[0], Bh[1], Bh[2], Bh[3], sbase + OFF_UH + boff + kk);
            LDSM4(Bl[0], Bl[1], Bl[2], Bl[3], sbase + OFF_UL + boff + kk);
            #pragma unroll
            for (int i = 0; i < 2; i++)
                #pragma unroll
                for (int j = 0; j < 2; j++) {
                    mma16816(a2c[i][j], Ah[i], Bh + j * 2);
                    mma16816(a2c[i][j], Al[i], Bh + j * 2);
                    mma16816(a2c[i][j], Ah[i], Bl + j * 2);
                }
        }

        {   // epilogue2: out = gelu(D2 + x), residual from gmem (float2)
            #pragma unroll
            for (int i = 0; i < 2; i++)
                #pragma unroll
                for (int j = 0; j < 2; j++) {
                    int px = nb + n_base + j * 8 + (lane & 3) * 2;
                    int o0 = m_base + i * 16 + (lane >> 2);
                    #pragma unroll
                    for (int half = 0; half < 2; half++) {
                        int oo = o0 + half * 8;
                        const float* xr = x + ((size_t)b * CHN + oo) * NPIX + px;
                        float* orow = out + ((size_t)b * CHN + oo) * NPIX + px;
                        float2 xv = *(const float2*)xr;
                        float2 r;
                        r.x = gelu_fast(a2c[i][j][half * 2 + 0] + xv.x);
                        r.y = gelu_fast(a2c[i][j][half * 2 + 1] + xv.y);
                        *(float2*)orow = r;
                    }
                }
        }
    }
}

// ============================================================================
extern "C" void kernel_launch(void* const* d_in, const int* in_sizes, int n_in,
                              void* d_out, int out_size) {
    const float* x     = (const float*)d_in[0];
    const float* qkv_w = (const float*)d_in[1];
    const float* o1_w  = (const float*)d_in[2];
    const float* o2_w  = (const float*)d_in[3];
    const float* klw   = (const float*)d_in[4];
    const float* klb   = (const float*)d_in[5];
    const float* vlw   = (const float*)d_in[6];
    const float* vlb   = (const float*)d_in[7];
    float* out = (float*)d_out;

    const int SMEM_A = 208896;
    const int SMEM_B = (2048 + 128 * 129) * (int)sizeof(float);
    const int SMEM_C = 208896;

    cudaFuncSetAttribute(kv_accum_kernel,   cudaFuncAttributeMaxDynamicSharedMemorySize, SMEM_A);
    cudaFuncSetAttribute(build_mats_kernel, cudaFuncAttributeMaxDynamicSharedMemorySize, SMEM_B);
    cudaFuncSetAttribute(mlp_kernel,        cudaFuncAttributeMaxDynamicSharedMemorySize, SMEM_C);

    zero_kv_kernel<<<32, 512>>>();
    prep_wkv_kernel<<<64, 512>>>(qkv_w);
    kv_accum_kernel<<<dim3(NPIX / (PXA * NCHA), BATCH), 512, SMEM_A>>>(
        x, klw, klb, vlw, vlb);
    build_mats_kernel<<<dim3(16, BATCH), 512, SMEM_B>>>(qkv_w, o1_w, o2_w);
    mlp_kernel<<<dim3(NPIX / (PXC * NCHC), BATCH), 1024, SMEM_C>>>(x, out);
}

// round 14
// speedup vs baseline: 1.1301x; 1.0454x over previous
#include <cuda_runtime.h>
#include <cuda_bf16.h>
#include <math.h>
#include <stdint.h>

#define BATCH  8
#define CHN    128
#define HEADS  8
#define HC     16
#define NPIX   65536
#define EPS    1e-5f

#define PXA    64      // kernel A pixels per chunk
#define NCHA   8       // chunks per CTA (A)  -> 512 px/CTA
#define PXC    64      // mlp pixels per chunk
#define NCHC   8       // chunks per CTA (C)  -> 512 px/CTA
#define WSTR   136     // bf16 row stride (272B): conflict-free ldmatrix
#define LNS    66      // LN buffer row stride (floats)

typedef unsigned long long ull;
typedef unsigned int u32;
typedef unsigned short u16;

// ---------------- persistent device scratch ----------------
__device__ float g_kv[BATCH * HEADS * HC * HC];                      // 16384 elems
__device__ __align__(16) __nv_bfloat16 g_wkv[2][256][WSTR];          // kv weights hi/lo
__device__ __align__(16) __nv_bfloat16 g_m1[BATCH][2][CHN][WSTR];    // fused M1 hi/lo
__device__ __align__(16) __nv_bfloat16 g_o2[2][CHN][WSTR];           // o2 hi/lo

// ---------------- helpers ----------------
static __device__ __forceinline__ ull fma2(ull a, ull b, ull c) {
    ull d;
    asm("fma.rn.f32x2 %0, %1, %2, %3;" : "=l"(d) : "l"(a), "l"(b), "l"(c));
    return d;
}
static __device__ __forceinline__ float2 unpack2(ull v) {
    float2 r;
    asm("mov.b64 {%0, %1}, %2;" : "=f"(r.x), "=f"(r.y) : "l"(v));
    return r;
}
static __device__ __forceinline__ float gelu_fast(float v) {
    float c = v * v;
    float t = v * (0.79788456f + 0.035677408f * c);
    float th;
    asm("tanh.approx.f32 %0, %1;" : "=f"(th) : "f"(t));
    return 0.5f * v * (1.f + th);
}
static __device__ __forceinline__ float sqrt_approx(float v) {
    float r;
    asm("sqrt.approx.f32 %0, %1;" : "=f"(r) : "f"(v));
    return r;
}
static __device__ __forceinline__ float rcp_approx(float v) {
    float r;
    asm("rcp.approx.f32 %0, %1;" : "=f"(r) : "f"(v));
    return r;
}
static __device__ __forceinline__ u32 pack_bf16x2(float a_hi, float a_lo) {
    u32 r;
    asm("cvt.rn.bf16x2.f32 %0, %1, %2;" : "=r"(r) : "f"(a_hi), "f"(a_lo));
    return r;
}
static __device__ __forceinline__ u32 smem_u32(const void* p) {
    u32 a;
    asm("{ .reg .u64 t; cvta.to.shared.u64 t, %1; cvt.u32.u64 %0, t; }" : "=r"(a) : "l"(p));
    return a;
}

#define LDSM4(r0, r1, r2, r3, a)                                           \
    asm volatile("ldmatrix.sync.aligned.m8n8.x4.shared.b16 {%0,%1,%2,%3}, [%4];" \
        : "=r"(r0), "=r"(r1), "=r"(r2), "=r"(r3) : "r"(a))

static __device__ __forceinline__ void mma16816(float* d, const u32* a, const u32* b) {
    asm volatile(
        "mma.sync.aligned.m16n8k16.row.col.f32.bf16.bf16.f32 "
        "{%0,%1,%2,%3}, {%4,%5,%6,%7}, {%8,%9}, {%0,%1,%2,%3};"
        : "+f"(d[0]), "+f"(d[1]), "+f"(d[2]), "+f"(d[3])
        : "r"(a[0]), "r"(a[1]), "r"(a[2]), "r"(a[3]), "r"(b[0]), "r"(b[1]));
}

static __device__ __forceinline__ void split_bf16(float w, __nv_bfloat16& hi, __nv_bfloat16& lo) {
    hi = __float2bfloat16(w);
    lo = __float2bfloat16(w - __bfloat162float(hi));
}
static __device__ __forceinline__ void split_pair(float v0, float v1, u32& h2, u32& l2) {
    h2 = pack_bf16x2(v1, v0);
    float h0 = __uint_as_float(h2 << 16);
    float h1 = __uint_as_float(h2 & 0xFFFF0000u);
    l2 = pack_bf16x2(v1 - h1, v0 - h0);
}

// ============================================================================
// Prep: zero kv accumulators, split k/v weight rows, split o2 (kv-independent).
// 64 blocks x 512 threads = 32768 = one thread per (o, c).
// ============================================================================
__global__ void prep_kernel(const float* __restrict__ qkv_w,
                            const float* __restrict__ o2_w) {
    int idx = blockIdx.x * blockDim.x + threadIdx.x;   // 32768
    if (idx < BATCH * HEADS * HC * HC) g_kv[idx] = 0.f;

    int o = idx >> 7, c = idx & 127;
    {   // k/v weight split: local row o -> qkv row (o>>5)*48+16+(o&31)
        int row = (o >> 5) * 48 + 16 + (o & 31);
        __nv_bfloat16 hi, lo;
        split_bf16(qkv_w[row * CHN + c], hi, lo);
        g_wkv[0][o][c] = hi;
        g_wkv[1][o][c] = lo;
    }
    if (o < CHN) {   // o2 split (first 16384 threads)
        __nv_bfloat16 hi, lo;
        split_bf16(o2_w[o * CHN + c], hi, lo);
        g_o2[0][o][c] = hi;
        g_o2[1][o][c] = lo;
    }
}

// ============================================================================
// Kernel A (R11 best): k,v GEMM (mma.sync bf16 3-term) + LN(16) + kv outer.
// 512 threads = 16 warps: 8(M) x 2(N); warp tile 32 out x 32 px; chunk 64 px.
// ============================================================================
__global__ void __launch_bounds__(512, 1) kv_accum_kernel(
    const float* __restrict__ x,
    const float* __restrict__ klw, const float* __restrict__ klb,
    const float* __restrict__ vlw, const float* __restrict__ vlb)
{
    extern __shared__ __align__(16) unsigned char sm[];
    const int OFF_WH = 0;          // 69632
    const int OFF_WL = 69632;      // weights end 139264
    const int OFF_XH = 139264;     // 17408
    const int OFF_XL = 156672;     // X end 174080
    const int OFF_LN = 139264;     // overlay: 256*LNS*4 = 67584, ends 206848
    const int OFF_LW = 206848;
    const int OFF_LB = 207872;     // total 208896

    const u32 sbase = smem_u32(sm);
    float* lnbuf = (float*)(sm + OFF_LN);
    float* lw = (float*)(sm + OFF_LW);
    float* lb = (float*)(sm + OFF_LB);

    const int tid = threadIdx.x;
    const int wid = tid >> 5, lane = tid & 31;
    const int b = blockIdx.y;
    const int n0 = blockIdx.x * (PXA * NCHA);

    {   // weight images -> smem (8704 float4 = 17*512)
        const float4* src = (const float4*)&g_wkv[0][0][0];
        float4* dst = (float4*)(sm + OFF_WH);
        #pragma unroll
        for (int i = 0; i < 17; i++) dst[tid + i * 512] = src[tid + i * 512];
    }
    if (tid < 256) {
        int o = tid, h = o >> 5, d = o & 15;
        if (o & 16) { lw[o] = vlw[h * HC + d]; lb[o] = vlb[h * HC + d]; }
        else        { lw[o] = klw[h * HC + d]; lb[o] = klb[h * HC + d]; }
    }

    const int wm = wid & 7, wn = wid >> 3;
    const int m_base = wm * 32, n_base = wn * 32;
    const u32 aoff = (u32)((m_base + (lane & 15)) * WSTR + (lane >> 4) * 8) * 2;
    const u32 boff = (u32)((n_base + (lane & 7) + (lane >> 4) * 8) * WSTR
                           + ((lane >> 3) & 1) * 8) * 2;

    const int lc2 = (tid & 63) * 2, lpx = (tid >> 6) * 8;
    const float* gx0 = x + ((size_t)b * CHN + lc2) * NPIX + lpx;
    const float* gx1 = gx0 + NPIX;
    const int ohead = wid & 7, ophalf = (wid >> 3) * 32;
    const int odd = lane >> 1, oe0 = (lane & 1) * 8;

    ull kvacc[8];
    #pragma unroll
    for (int t = 0; t < 8; t++) kvacc[t] = 0ull;

    // prefetch chunk 0
    float vv0[8], vv1[8];
    {
        const float4* g0 = (const float4*)(gx0 + n0);
        const float4* g1 = (const float4*)(gx1 + n0);
        float4 a0 = g0[0], a1 = g0[1], c0 = g1[0], c1 = g1[1];
        vv0[0]=a0.x; vv0[1]=a0.y; vv0[2]=a0.z; vv0[3]=a0.w;
        vv0[4]=a1.x; vv0[5]=a1.y; vv0[6]=a1.z; vv0[7]=a1.w;
        vv1[0]=c0.x; vv1[1]=c0.y; vv1[2]=c0.z; vv1[3]=c0.w;
        vv1[4]=c1.x; vv1[5]=c1.y; vv1[6]=c1.z; vv1[7]=c1.w;
    }

    for (int ch = 0; ch < NCHA; ch++) {
        __syncthreads();

        {   // current chunk regs -> X split (packed 4B stores)
            #pragma unroll
            for (int j = 0; j < 8; j++) {
                u32 h2, l2;
                split_pair(vv0[j], vv1[j], h2, l2);
                int boffj = ((lpx + j) * WSTR + lc2) * 2;
                *(u32*)(sm + OFF_XH + boffj) = h2;
                *(u32*)(sm + OFF_XL + boffj) = l2;
            }
        }
        if (ch + 1 < NCHA) {
            const float4* g0 = (const float4*)(gx0 + n0 + (ch + 1) * PXA);
            const float4* g1 = (const float4*)(gx1 + n0 + (ch + 1) * PXA);
            float4 a0 = g0[0], a1 = g0[1], c0 = g1[0], c1 = g1[1];
            vv0[0]=a0.x; vv0[1]=a0.y; vv0[2]=a0.z; vv0[3]=a0.w;
            vv0[4]=a1.x; vv0[5]=a1.y; vv0[6]=a1.z; vv0[7]=a1.w;
            vv1[0]=c0.x; vv1[1]=c0.y; vv1[2]=c0.z; vv1[3]=c0.w;
            vv1[4]=c1.x; vv1[5]=c1.y; vv1[6]=c1.z; vv1[7]=c1.w;
        }
        __syncthreads();

        float acc[2][4][4];
        #pragma unroll
        for (int i = 0; i < 2; i++)
            #pragma unroll
            for (int j = 0; j < 4; j++)
                #pragma unroll
                for (int q = 0; q < 4; q++) acc[i][j][q] = 0.f;

        #pragma unroll
        for (int ks = 0; ks < 8; ks++) {
            const u32 kk = ks * 32;
            u32 Ah[2][4], Al[2][4], Bh[8], Bl[8];
            LDSM4(Ah[0][0], Ah[0][1], Ah[0][2], Ah[0][3], sbase + OFF_WH + aoff + kk);
            LDSM4(Ah[1][0], Ah[1][1], Ah[1][2], Ah[1][3], sbase + OFF_WH + aoff + kk + 16 * WSTR * 2);
            LDSM4(Al[0][0], Al[0][1], Al[0][2], Al[0][3], sbase + OFF_WL + aoff + kk);
            LDSM4(Al[1][0], Al[1][1], Al[1][2], Al[1][3], sbase + OFF_WL + aoff + kk + 16 * WSTR * 2);
            LDSM4(Bh[0], Bh[1], Bh[2], Bh[3], sbase + OFF_XH + boff + kk);
            LDSM4(Bh[4], Bh[5], Bh[6], Bh[7], sbase + OFF_XH + boff + kk + 16 * WSTR * 2);
            LDSM4(Bl[0], Bl[1], Bl[2], Bl[3], sbase + OFF_XL + boff + kk);
            LDSM4(Bl[4], Bl[5], Bl[6], Bl[7], sbase + OFF_XL + boff + kk + 16 * WSTR * 2);
            #pragma unroll
            for (int i = 0; i < 2; i++) {
                #pragma unroll
                for (int j = 0; j < 4; j++) {
                    mma16816(acc[i][j], Ah[i], Bh + j * 2);
                    mma16816(acc[i][j], Al[i], Bh + j * 2);
                    mma16816(acc[i][j], Ah[i], Bl + j * 2);
                }
            }
        }
        __syncthreads();

        #pragma unroll
        for (int i = 0; i < 2; i++) {
            #pragma unroll
            for (int j = 0; j < 4; j++) {
                int px = n_base + j * 8 + (lane & 3) * 2;
                int o0 = m_base + i * 16 + (lane >> 2);
                *(float2*)&lnbuf[o0 * LNS + px]       = make_float2(acc[i][j][0], acc[i][j][1]);
                *(float2*)&lnbuf[(o0 + 8) * LNS + px] = make_float2(acc[i][j][2], acc[i][j][3]);
            }
        }
        __syncthreads();

        {   // LayerNorm: 1024 tasks = 64 px x 8 heads x {k,v}; 2 per thread
            int p = tid & 63, hh = (tid >> 6) & 7;
            #pragma unroll
            for (int part = 0; part < 2; part++) {
                int rbase = hh * 32 + part * 16;
                float t[16]; float s = 0.f;
                #pragma unroll
                for (int d = 0; d < 16; d++) { t[d] = lnbuf[(rbase + d) * LNS + p]; s += t[d]; }
                float m = s * (1.f / 16.f);
                float var = 0.f;
                #pragma unroll
                for (int d = 0; d < 16; d++) { float dv = t[d] - m; var += dv * dv; }
                float inv = rcp_approx(sqrt_approx(var * (1.f / 15.f)) + EPS);
                #pragma unroll
                for (int d = 0; d < 16; d++)
                    lnbuf[(rbase + d) * LNS + p] =
                        lw[rbase + d] * ((t[d] - m) * inv) + lb[rbase + d];
            }
        }
        __syncthreads();

        {   // kv outer product (f32x2), 32 px per warp
            const float* kr = &lnbuf[(ohead * 32 + odd) * LNS + ophalf];
            #pragma unroll
            for (int p = 0; p < 32; p += 2) {
                ull k2 = *(const ull*)&kr[p];
                #pragma unroll
                for (int t = 0; t < 8; t++) {
                    ull v2 = *(const ull*)&lnbuf[(ohead * 32 + 16 + oe0 + t) * LNS + ophalf + p];
                    kvacc[t] = fma2(k2, v2, kvacc[t]);
                }
            }
        }
    }

    #pragma unroll
    for (int t = 0; t < 8; t++) {
        float2 v = unpack2(kvacc[t]);
        atomicAdd(&g_kv[((b * HEADS + ohead) * HC + odd) * HC + oe0 + t], v.x + v.y);
    }
}

// ============================================================================
// Kernel B (16-slice best): M1[b] = o1_w @ (A + I); bf16 hi/lo images.
// ============================================================================
__global__ void build_mats_kernel(const float* __restrict__ qkv_w,
                                  const float* __restrict__ o1_w)
{
    extern __shared__ float smf[];
    float* kvs = smf;           // 2048
    float* As  = smf + 2048;    // [128][129]
    const int tid = threadIdx.x;
    const int slice = blockIdx.x;   // 0..15 -> 8 M1 rows each
    const int b     = blockIdx.y;

    for (int i = tid; i < HEADS * HC * HC; i += 512)
        kvs[i] = g_kv[b * HEADS * HC * HC + i] * (1.f / NPIX);
    __syncthreads();

    for (int idx = tid; idx < CHN * CHN; idx += 512) {
        int j = idx >> 7, c = idx & 127;
        int h = j >> 4, e = j & 15;
        float s = 0.f;
        #pragma unroll
        for (int d = 0; d < HC; d++)
            s += qkv_w[(h * 48 + d) * CHN + c] * kvs[(h * HC + d) * HC + e];
        As[j * 129 + c] = s;
    }
    __syncthreads();

    for (int idx = tid; idx < 8 * CHN; idx += 512) {
        int o = slice * 8 + (idx >> 7), c = idx & 127;
        float s = o1_w[o * CHN + c];   // identity term
        #pragma unroll 8
        for (int j = 0; j < CHN; j++)
            s += o1_w[o * CHN + j] * As[j * 129 + c];
        __nv_bfloat16 hi, lo;
        split_bf16(s, hi, lo);
        g_m1[b][0][o][c] = hi;
        g_m1[b][1][o][c] = lo;
    }
}

// ============================================================================
// Kernel C (R11 best): out = gelu( o2 @ gelu( M1[b] @ x ) + x ).
// 512 threads = 16 warps: 4(M) x 4(N); warp tile 32 out x 16 px; chunk 64 px.
// X and U separate; epilogue2 residual reconstructed from X smem.
// ============================================================================
__global__ void __launch_bounds__(512, 1) mlp_kernel(
    const float* __restrict__ x, float* __restrict__ out)
{
    extern __shared__ __align__(16) unsigned char sm[];
    const int OFF_M1H = 0;          // 34816
    const int OFF_M1L = 34816;
    const int OFF_O2H = 69632;
    const int OFF_O2L = 104448;     // weights end 139264
    const int OFF_XH  = 139264;     // 17408
    const int OFF_XL  = 156672;     // X end 174080
    const int OFF_UH  = 174080;
    const int OFF_UL  = 191488;     // total 208896

    const u32 sbase = smem_u32(sm);
    const int tid = threadIdx.x;
    const int wid = tid >> 5, lane = tid & 31;
    const int b = blockIdx.y;
    const int n0 = blockIdx.x * (PXC * NCHC);

    {   // weight images -> smem: 4352 float4 each pair
        const float4* s1 = (const float4*)&g_m1[b][0][0][0];
        const float4* s2 = (const float4*)&g_o2[0][0][0];
        float4* d1 = (float4*)(sm + OFF_M1H);
        float4* d2 = (float4*)(sm + OFF_O2H);
        #pragma unroll
        for (int i = 0; i < 8; i++) {
            d1[tid + i * 512] = s1[tid + i * 512];
            d2[tid + i * 512] = s2[tid + i * 512];
        }
        if (tid < 256) {
            d1[tid + 4096] = s1[tid + 4096];
            d2[tid + 4096] = s2[tid + 4096];
        }
    }

    const int wm = wid & 3, wn = wid >> 2;
    const int m_base = wm * 32, n_base = wn * 16;
    const u32 aoff = (u32)((m_base + (lane & 15)) * WSTR + (lane >> 4) * 8) * 2;
    const u32 boff = (u32)((n_base + (lane & 7) + (lane >> 4) * 8) * WSTR
                           + ((lane >> 3) & 1) * 8) * 2;

    const int lc2 = (tid & 63) * 2, lpx = (tid >> 6) * 8;
    const float* gx0 = x + ((size_t)b * CHN + lc2) * NPIX + lpx;
    const float* gx1 = gx0 + NPIX;

    // prefetch chunk 0
    float vv0[8], vv1[8];
    {
        const float4* g0 = (const float4*)(gx0 + n0);
        const float4* g1 = (const float4*)(gx1 + n0);
        float4 a0 = g0[0], a1 = g0[1], c0 = g1[0], c1 = g1[1];
        vv0[0]=a0.x; vv0[1]=a0.y; vv0[2]=a0.z; vv0[3]=a0.w;
        vv0[4]=a1.x; vv0[5]=a1.y; vv0[6]=a1.z; vv0[7]=a1.w;
        vv1[0]=c0.x; vv1[1]=c0.y; vv1[2]=c0.z; vv1[3]=c0.w;
        vv1[4]=c1.x; vv1[5]=c1.y; vv1[6]=c1.z; vv1[7]=c1.w;
    }

    for (int ch = 0; ch < NCHC; ch++) {
        const int nb = n0 + ch * PXC;
        {   // current chunk regs -> X split (packed 4B stores)
            #pragma unroll
            for (int j = 0; j < 8; j++) {
                u32 h2, l2;
                split_pair(vv0[j], vv1[j], h2, l2);
                int boffj = ((lpx + j) * WSTR + lc2) * 2;
                *(u32*)(sm + OFF_XH + boffj) = h2;
                *(u32*)(sm + OFF_XL + boffj) = l2;
            }
        }
        if (ch + 1 < NCHC) {   // prefetch next chunk
            const float4* g0 = (const float4*)(gx0 + n0 + (ch + 1) * PXC);
            const float4* g1 = (const float4*)(gx1 + n0 + (ch + 1) * PXC);
            float4 a0 = g0[0], a1 = g0[1], c0 = g1[0], c1 = g1[1];
            vv0[0]=a0.x; vv0[1]=a0.y; vv0[2]=a0.z; vv0[3]=a0.w;
            vv0[4]=a1.x; vv0[5]=a1.y; vv0[6]=a1.z; vv0[7]=a1.w;
            vv1[0]=c0.x; vv1[1]=c0.y; vv1[2]=c0.z; vv1[3]=c0.w;
            vv1[4]=c1.x; vv1[5]=c1.y; vv1[6]=c1.z; vv1[7]=c1.w;
        }
        __syncthreads();

        // ---- GEMM1: D1 = M1 @ x ----
        float a1c[2][2][4];
        #pragma unroll
        for (int i = 0; i < 2; i++)
            #pragma unroll
            for (int j = 0; j < 2; j++)
                #pragma unroll
                for (int q = 0; q < 4; q++) a1c[i][j][q] = 0.f;

        #pragma unroll
        for (int ks = 0; ks < 8; ks++) {
            const u32 kk = ks * 32;
            u32 Ah[2][4], Al[2][4], Bh[4], Bl[4];
            LDSM4(Ah[0][0], Ah[0][1], Ah[0][2], Ah[0][3], sbase + OFF_M1H + aoff + kk);
            LDSM4(Ah[1][0], Ah[1][1], Ah[1][2], Ah[1][3], sbase + OFF_M1H + aoff + kk + 16 * WSTR * 2);
            LDSM4(Al[0][0], Al[0][1], Al[0][2], Al[0][3], sbase + OFF_M1L + aoff + kk);
            LDSM4(Al[1][0], Al[1][1], Al[1][2], Al[1][3], sbase + OFF_M1L + aoff + kk + 16 * WSTR * 2);
            LDSM4(Bh[0], Bh[1], Bh[2], Bh[3], sbase + OFF_XH + boff + kk);
            LDSM4(Bl[0], Bl[1], Bl[2], Bl[3], sbase + OFF_XL + boff + kk);
            #pragma unroll
            for (int i = 0; i < 2; i++)
                #pragma unroll
                for (int j = 0; j < 2; j++) {
                    mma16816(a1c[i][j], Ah[i], Bh + j * 2);
                    mma16816(a1c[i][j], Al[i], Bh + j * 2);
                    mma16816(a1c[i][j], Ah[i], Bl + j * 2);
                }
        }

        {   // epilogue1: u = gelu(D1), split, store transposed [px][chan] -> U
            __nv_bfloat16* uh = (__nv_bfloat16*)(sm + OFF_UH);
            __nv_bfloat16* ul = (__nv_bfloat16*)(sm + OFF_UL);
            #pragma unroll
            for (int i = 0; i < 2; i++)
                #pragma unroll
                for (int j = 0; j < 2; j++) {
                    int px = n_base + j * 8 + (lane & 3) * 2;
                    int o0 = m_base + i * 16 + (lane >> 2);
                    #pragma unroll
                    for (int q = 0; q < 4; q++) {
                        int pp = px + (q & 1);
                        int oo = o0 + (q >> 1) * 8;
                        float u = gelu_fast(a1c[i][j][q]);
                        __nv_bfloat16 hi, lo;
                        split_bf16(u, hi, lo);
                        uh[pp * WSTR + oo] = hi;
                        ul[pp * WSTR + oo] = lo;
                    }
                }
        }
        __syncthreads();

        // ---- GEMM2: D2 = o2 @ u ----
        float a2c[2][2][4];
        #pragma unroll
        for (int i = 0; i < 2; i++)
            #pragma unroll
            for (int j = 0; j < 2; j++)
                #pragma unroll
                for (int q = 0; q < 4; q++) a2c[i][j][q] = 0.f;

        #pragma unroll
        for (int ks = 0; ks < 8; ks++) {
            const u32 kk = ks * 32;
            u32 Ah[2][4], Al[2][4], Bh[4], Bl[4];
            LDSM4(Ah[0][0], Ah[0][1], Ah[0][2], Ah[0][3], sbase + OFF_O2H + aoff + kk);
            LDSM4(Ah[1][0], Ah[1][1], Ah[1][2], Ah[1][3], sbase + OFF_O2H + aoff + kk + 16 * WSTR * 2);
            LDSM4(Al[0][0], Al[0][1], Al[0][2], Al[0][3], sbase + OFF_O2L + aoff + kk);
            LDSM4(Al[1][0], Al[1][1], Al[1][2], Al[1][3], sbase + OFF_O2L + aoff + kk + 16 * WSTR * 2);
            LDSM4(Bh[0], Bh[1], Bh[2], Bh[3], sbase + OFF_UH + boff + kk);
            LDSM4(Bl[0], Bl[1], Bl[2], Bl[3], sbase + OFF_UL + boff + kk);
            #pragma unroll
            for (int i = 0; i < 2; i++)
                #pragma unroll
                for (int j = 0; j < 2; j++) {
                    mma16816(a2c[i][j], Ah[i], Bh + j * 2);
                    mma16816(a2c[i][j], Al[i], Bh + j * 2);
                    mma16816(a2c[i][j], Ah[i], Bl + j * 2);
                }
        }

        {   // epilogue2: out = gelu(D2 + x); residual rebuilt from X smem (hi+lo)
            const __nv_bfloat16* xh = (const __nv_bfloat16*)(sm + OFF_XH);
            const __nv_bfloat16* xl = (const __nv_bfloat16*)(sm + OFF_XL);
            #pragma unroll
            for (int i = 0; i < 2; i++)
                #pragma unroll
                for (int j = 0; j < 2; j++) {
                    int pxl = n_base + j * 8 + (lane & 3) * 2;
                    int o0 = m_base + i * 16 + (lane >> 2);
                    #pragma unroll
                    for (int half = 0; half < 2; half++) {
                        int oo = o0 + half * 8;
                        u32 h0 = *(const u16*)&xh[pxl * WSTR + oo];
                        u32 l0 = *(const u16*)&xl[pxl * WSTR + oo];
                        u32 h1 = *(const u16*)&xh[(pxl + 1) * WSTR + oo];
                        u32 l1 = *(const u16*)&xl[(pxl + 1) * WSTR + oo];
                        float xv0 = __uint_as_float(h0 << 16) + __uint_as_float(l0 << 16);
                        float xv1 = __uint_as_float(h1 << 16) + __uint_as_float(l1 << 16);
                        float2 r;
                        r.x = gelu_fast(a2c[i][j][half * 2 + 0] + xv0);
                        r.y = gelu_fast(a2c[i][j][half * 2 + 1] + xv1);
                        *(float2*)(out + ((size_t)b * CHN + oo) * NPIX + nb + pxl) = r;
                    }
                }
        }
        __syncthreads();   // U reads (GEMM2) + X reads (E2) done before next chunk
    }
}

// ============================================================================
extern "C" void kernel_launch(void* const* d_in, const int* in_sizes, int n_in,
                              void* d_out, int out_size) {
    const float* x     = (const float*)d_in[0];
    const float* qkv_w = (const float*)d_in[1];
    const float* o1_w  = (const float*)d_in[2];
    const float* o2_w  = (const float*)d_in[3];
    const float* klw   = (const float*)d_in[4];
    const float* klb   = (const float*)d_in[5];
    const float* vlw   = (const float*)d_in[6];
    const float* vlb   = (const float*)d_in[7];
    float* out = (float*)d_out;

    const int SMEM_A = 208896;
    const int SMEM_B = (2048 + 128 * 129) * (int)sizeof(float);
    const int SMEM_C = 208896;

    cudaFuncSetAttribute(kv_accum_kernel,   cudaFuncAttributeMaxDynamicSharedMemorySize, SMEM_A);
    cudaFuncSetAttribute(build_mats_kernel, cudaFuncAttributeMaxDynamicSharedMemorySize, SMEM_B);
    cudaFuncSetAttribute(mlp_kernel,        cudaFuncAttributeMaxDynamicSharedMemorySize, SMEM_C);

    prep_kernel<<<64, 512>>>(qkv_w, o2_w);
    kv_accum_kernel<<<dim3(NPIX / (PXA * NCHA), BATCH), 512, SMEM_A>>>(
        x, klw, klb, vlw, vlb);
    build_mats_kernel<<<dim3(16, BATCH), 512, SMEM_B>>>(qkv_w, o1_w);
    mlp_kernel<<<dim3(NPIX / (PXC * NCHC), BATCH), 512, SMEM_C>>>(x, out);
}